// round 3
// baseline (speedup 1.0000x reference)
#include <cuda_runtime.h>

// MK_MMDLoss: MMD between x,y (4,256,32,32) with 5-sigma Gaussian kernel mix.
// N=4096 rows, C=256 feats. result = mean_xx + mean_yy - 2*mean_xy.
//
// Strategy R1: fused fp32 FFMA tiled "GEMM" (128x128x8) + exp epilogue.
//  - No transpose pass: row r=(b*1024+hw), feat c lives at b*262144+c*1024+hw,
//    so a 128-row x 8-k tile is 8 contiguous 128-float segments (coalesced).
//  - xx/yy symmetric: only upper-triangle tile pairs, off-diag weight 2.
//  - Diagonal exactness: row-norm kernel and GEMM use identical sequential
//    fmaf chains -> dist(i,i) == 0 bitwise -> diag Sexp = 5 exactly.
//  - Per-block fp32 partial -> atomicAdd(double) -> finalize divides by N^2.

#define NR   4096
#define CD   256
#define HWD  1024
#define BM   128
#define BN   128
#define BK   8
#define TM   8
#define TN   8
#define NTILE (NR / BM)   // 32

__device__ float  g_x2[NR];
__device__ float  g_y2[NR];
__device__ double g_acc;

// One thread per row: squared norm, sequential fmaf over c (matches GEMM order).
__global__ void mmd_norm_kernel(const float* __restrict__ x,
                                const float* __restrict__ y) {
    int r = blockIdx.x * blockDim.x + threadIdx.x;
    if (r == 0 && blockIdx.y == 0) g_acc = 0.0;   // stream-ordered before mains
    const float* p = blockIdx.y ? y : x;
    int b  = r >> 10;
    int hw = r & 1023;
    const float* base = p + (size_t)b * (CD * HWD) + hw;
    float s = 0.f;
#pragma unroll 8
    for (int c = 0; c < CD; ++c) {
        float v = base[(size_t)c * HWD];
        s = fmaf(v, v, s);
    }
    (blockIdx.y ? g_y2 : g_x2)[r] = s;
}

// mode 0: xx (sym, +1)   mode 1: yy (sym, +1)   mode 2: xy (full, -2)
__global__ void __launch_bounds__(256, 2) mmd_main_kernel(
    const float* __restrict__ x, const float* __restrict__ y,
    const float* __restrict__ sig, int mode)
{
    const float *A, *B, *a2, *b2;
    double weight;
    int sym;
    if (mode == 0)      { A = x; B = x; a2 = g_x2; b2 = g_x2; weight =  1.0; sym = 1; }
    else if (mode == 1) { A = y; B = y; a2 = g_y2; b2 = g_y2; weight =  1.0; sym = 1; }
    else                { A = x; B = y; a2 = g_x2; b2 = g_y2; weight = -2.0; sym = 0; }

    int ti, tj;
    if (sym) {
        int b = blockIdx.x; ti = 0;
        while (b >= NTILE - ti) { b -= NTILE - ti; ++ti; }
        tj = ti + b;
    } else {
        ti = blockIdx.x / NTILE;
        tj = blockIdx.x % NTILE;
    }

    __shared__ float As[BK][BM];
    __shared__ float Bs[BK][BN];
    __shared__ float sred[256];

    int tid = threadIdx.x;
    int tx  = tid & 15;        // 0..15
    int ty  = tid >> 4;        // 0..15
    int lk  = tid >> 5;        // 0..7  (k within BK for loads)
    int lm  = (tid & 31) << 2; // 0..124 step 4 (m within tile)

    int rowA0 = ti * BM;
    int rowB0 = tj * BN;
    // tile base address in (B,C,H,W) layout: b*262144 + c*1024 + hw
    size_t baseA = (size_t)(rowA0 >> 10) * (CD * HWD) + (rowA0 & 1023);
    size_t baseB = (size_t)(rowB0 >> 10) * (CD * HWD) + (rowB0 & 1023);

    float acc[TM][TN];
#pragma unroll
    for (int i = 0; i < TM; ++i)
#pragma unroll
        for (int j = 0; j < TN; ++j) acc[i][j] = 0.f;

    for (int k0 = 0; k0 < CD; k0 += BK) {
        float4 va = *(const float4*)(A + baseA + (size_t)(k0 + lk) * HWD + lm);
        float4 vb = *(const float4*)(B + baseB + (size_t)(k0 + lk) * HWD + lm);
        *(float4*)&As[lk][lm] = va;
        *(float4*)&Bs[lk][lm] = vb;
        __syncthreads();
#pragma unroll
        for (int k = 0; k < BK; ++k) {
            float ra[TM], rb[TN];
#pragma unroll
            for (int i = 0; i < TM; ++i) ra[i] = As[k][ty * TM + i];
#pragma unroll
            for (int j = 0; j < TN; ++j) rb[j] = Bs[k][tx * TN + j];
#pragma unroll
            for (int i = 0; i < TM; ++i)
#pragma unroll
                for (int j = 0; j < TN; ++j)
                    acc[i][j] = fmaf(ra[i], rb[j], acc[i][j]);
        }
        __syncthreads();
    }

    // betas = 1/(2*sigma)
    float bet[5];
#pragma unroll
    for (int s = 0; s < 5; ++s) bet[s] = 0.5f / __ldg(&sig[s]);

    float part = 0.f;
#pragma unroll
    for (int i = 0; i < TM; ++i) {
        float a2v = a2[rowA0 + ty * TM + i];
#pragma unroll
        for (int j = 0; j < TN; ++j) {
            float b2v = b2[rowB0 + tx * TN + j];
            float d = a2v + b2v - 2.0f * acc[i][j];
            d = fmaxf(d, 0.f);
            float s = 0.f;
#pragma unroll
            for (int k = 0; k < 5; ++k) s += __expf(-bet[k] * d);
            part += s;
        }
    }
    if (sym && ti != tj) part *= 2.0f;

    sred[tid] = part;
    __syncthreads();
    for (int s = 128; s > 0; s >>= 1) {
        if (tid < s) sred[tid] += sred[tid + s];
        __syncthreads();
    }
    if (tid == 0) atomicAdd(&g_acc, weight * (double)sred[0]);
}

__global__ void mmd_finalize(float* __restrict__ out) {
    out[0] = (float)(g_acc / ((double)NR * (double)NR));
}

extern "C" void kernel_launch(void* const* d_in, const int* in_sizes, int n_in,
                              void* d_out, int out_size) {
    const float* x   = (const float*)d_in[0];
    const float* y   = (const float*)d_in[1];
    const float* sig = (const float*)d_in[2];
    float* out = (float*)d_out;

    mmd_norm_kernel<<<dim3(NR / 256, 2), 256>>>(x, y);

    int nsym  = NTILE * (NTILE + 1) / 2;  // 528
    int nfull = NTILE * NTILE;            // 1024
    mmd_main_kernel<<<nsym,  256>>>(x, y, sig, 0);
    mmd_main_kernel<<<nsym,  256>>>(x, y, sig, 1);
    mmd_main_kernel<<<nfull, 256>>>(x, y, sig, 2);

    mmd_finalize<<<1, 1>>>(out);
}

// round 4
// speedup vs baseline: 1.0079x; 1.0079x over previous
#include <cuda_runtime.h>

// MK_MMDLoss: MMD between x,y (4,256,32,32), 5-sigma Gaussian kernel mix.
// R3: inner product rewritten with packed fma.rn.f32x2 (FFMA2) -> 2x fp32 rate.
//  - Per-lane FMA rounding identical to scalar fmaf, same k-order as norm
//    kernel -> diag dist stays bitwise 0 -> diag Sexp = 5 exactly.
//  - xx/yy upper-triangle tiles (weight 2 off-diag), xy full grid.

#define NR   4096
#define CD   256
#define HWD  1024
#define BM   128
#define BN   128
#define BK   8
#define TM   8
#define TN   8
#define NTILE (NR / BM)   // 32

typedef unsigned long long u64;

__device__ float  g_x2[NR];
__device__ float  g_y2[NR];
__device__ double g_acc;

__device__ __forceinline__ u64 dupf(float x) {
    u64 r;
    unsigned u = __float_as_uint(x);
    asm("mov.b64 %0, {%1, %1};" : "=l"(r) : "r"(u));
    return r;
}
__device__ __forceinline__ void ffma2(u64& d, u64 a, u64 b) {
    asm("fma.rn.f32x2 %0, %1, %2, %0;" : "+l"(d) : "l"(a), "l"(b));
}
__device__ __forceinline__ void unpack2(u64 v, float& lo, float& hi) {
    unsigned ulo, uhi;
    asm("mov.b64 {%0, %1}, %2;" : "=r"(ulo), "=r"(uhi) : "l"(v));
    lo = __uint_as_float(ulo);
    hi = __uint_as_float(uhi);
}

// One thread per row: squared norm, sequential fmaf over c (matches GEMM order).
__global__ void mmd_norm_kernel(const float* __restrict__ x,
                                const float* __restrict__ y) {
    int r = blockIdx.x * blockDim.x + threadIdx.x;
    if (r == 0 && blockIdx.y == 0) g_acc = 0.0;   // stream-ordered before mains
    const float* p = blockIdx.y ? y : x;
    int b  = r >> 10;
    int hw = r & 1023;
    const float* base = p + (size_t)b * (CD * HWD) + hw;
    float s = 0.f;
#pragma unroll 8
    for (int c = 0; c < CD; ++c) {
        float v = base[(size_t)c * HWD];
        s = fmaf(v, v, s);
    }
    (blockIdx.y ? g_y2 : g_x2)[r] = s;
}

// mode 0: xx (sym, +1)   mode 1: yy (sym, +1)   mode 2: xy (full, -2)
__global__ void __launch_bounds__(256, 2) mmd_main_kernel(
    const float* __restrict__ x, const float* __restrict__ y,
    const float* __restrict__ sig, int mode)
{
    const float *A, *B, *a2, *b2;
    double weight;
    int sym;
    if (mode == 0)      { A = x; B = x; a2 = g_x2; b2 = g_x2; weight =  1.0; sym = 1; }
    else if (mode == 1) { A = y; B = y; a2 = g_y2; b2 = g_y2; weight =  1.0; sym = 1; }
    else                { A = x; B = y; a2 = g_x2; b2 = g_y2; weight = -2.0; sym = 0; }

    int ti, tj;
    if (sym) {
        int b = blockIdx.x; ti = 0;
        while (b >= NTILE - ti) { b -= NTILE - ti; ++ti; }
        tj = ti + b;
    } else {
        ti = blockIdx.x / NTILE;
        tj = blockIdx.x % NTILE;
    }

    __shared__ __align__(16) float As[BK][BM];
    __shared__ __align__(16) float Bs[BK][BN];
    __shared__ float sred[256];

    int tid = threadIdx.x;
    int tx  = tid & 15;        // 0..15
    int ty  = tid >> 4;        // 0..15
    int lk  = tid >> 5;        // 0..7  (k within BK for loads)
    int lm  = (tid & 31) << 2; // 0..124 step 4 (m within tile)

    int rowA0 = ti * BM;
    int rowB0 = tj * BN;
    // tile base address in (B,C,H,W) layout: b*262144 + c*1024 + hw
    size_t baseA = (size_t)(rowA0 >> 10) * (CD * HWD) + (rowA0 & 1023);
    size_t baseB = (size_t)(rowB0 >> 10) * (CD * HWD) + (rowB0 & 1023);

    // Packed accumulators: acc2[i][jp] holds columns (2jp, 2jp+1) as f32x2.
    u64 acc2[TM][TN / 2];
#pragma unroll
    for (int i = 0; i < TM; ++i)
#pragma unroll
        for (int j = 0; j < TN / 2; ++j) acc2[i][j] = 0ull;

    for (int k0 = 0; k0 < CD; k0 += BK) {
        float4 va = *(const float4*)(A + baseA + (size_t)(k0 + lk) * HWD + lm);
        float4 vb = *(const float4*)(B + baseB + (size_t)(k0 + lk) * HWD + lm);
        *(float4*)&As[lk][lm] = va;
        *(float4*)&Bs[lk][lm] = vb;
        __syncthreads();
#pragma unroll
        for (int k = 0; k < BK; ++k) {
            // B fragment: already in packed-pair bit layout in SMEM.
            ulonglong2 bq0 = *(const ulonglong2*)&Bs[k][tx * TN];
            ulonglong2 bq1 = *(const ulonglong2*)&Bs[k][tx * TN + 4];
            u64 rb2[4] = { bq0.x, bq0.y, bq1.x, bq1.y };
            // A fragment: lane-duplicated scalars.
            float4 af0 = *(const float4*)&As[k][ty * TM];
            float4 af1 = *(const float4*)&As[k][ty * TM + 4];
            u64 ra2[8];
            ra2[0] = dupf(af0.x); ra2[1] = dupf(af0.y);
            ra2[2] = dupf(af0.z); ra2[3] = dupf(af0.w);
            ra2[4] = dupf(af1.x); ra2[5] = dupf(af1.y);
            ra2[6] = dupf(af1.z); ra2[7] = dupf(af1.w);
#pragma unroll
            for (int i = 0; i < TM; ++i)
#pragma unroll
                for (int jp = 0; jp < TN / 2; ++jp)
                    ffma2(acc2[i][jp], ra2[i], rb2[jp]);
        }
        __syncthreads();
    }

    // betas = 1/(2*sigma)
    float bet[5];
#pragma unroll
    for (int s = 0; s < 5; ++s) bet[s] = 0.5f / __ldg(&sig[s]);

    float part = 0.f;
#pragma unroll
    for (int i = 0; i < TM; ++i) {
        float a2v = a2[rowA0 + ty * TM + i];
#pragma unroll
        for (int jp = 0; jp < TN / 2; ++jp) {
            float accl, acch;
            unpack2(acc2[i][jp], accl, acch);
#pragma unroll
            for (int h = 0; h < 2; ++h) {
                float accv = h ? acch : accl;
                float b2v = b2[rowB0 + tx * TN + 2 * jp + h];
                float d = a2v + b2v - 2.0f * accv;
                d = fmaxf(d, 0.f);
                float s = 0.f;
#pragma unroll
                for (int k = 0; k < 5; ++k) s += __expf(-bet[k] * d);
                part += s;
            }
        }
    }
    if (sym && ti != tj) part *= 2.0f;

    sred[tid] = part;
    __syncthreads();
    for (int s = 128; s > 0; s >>= 1) {
        if (tid < s) sred[tid] += sred[tid + s];
        __syncthreads();
    }
    if (tid == 0) atomicAdd(&g_acc, weight * (double)sred[0]);
}

__global__ void mmd_finalize(float* __restrict__ out) {
    out[0] = (float)(g_acc / ((double)NR * (double)NR));
}

extern "C" void kernel_launch(void* const* d_in, const int* in_sizes, int n_in,
                              void* d_out, int out_size) {
    const float* x   = (const float*)d_in[0];
    const float* y   = (const float*)d_in[1];
    const float* sig = (const float*)d_in[2];
    float* out = (float*)d_out;

    mmd_norm_kernel<<<dim3(NR / 256, 2), 256>>>(x, y);

    int nsym  = NTILE * (NTILE + 1) / 2;  // 528
    int nfull = NTILE * NTILE;            // 1024
    mmd_main_kernel<<<nsym,  256>>>(x, y, sig, 0);
    mmd_main_kernel<<<nsym,  256>>>(x, y, sig, 1);
    mmd_main_kernel<<<nfull, 256>>>(x, y, sig, 2);

    mmd_finalize<<<1, 1>>>(out);
}

// round 6
// speedup vs baseline: 3.0070x; 2.9833x over previous
#include <cuda_runtime.h>
#include <cuda_bf16.h>
#include <cstdint>

// MK_MMDLoss R5: portable tensor cores (ldmatrix + mma.sync m16n8k16 bf16,
// fp32 accum) since the harness targets plain sm_103 (no 'a' -> no tcgen05).
// Three 4096x4096x256 Grams; diagonal excluded per-element and added
// analytically; fp32 row norms from original data.

#define NR    4096
#define CD    256
#define HWD   1024
#define BM    128
#define NTILE (NR / BM)     // 32
#define PADK  264           // smem row: 256 bf16 + 8 pad
#define ROWB  (PADK * 2)    // 528 bytes (mult of 16; 528 mod 128 = 16 -> no conflicts)

__device__ __align__(16) __nv_bfloat16 g_xb[NR * CD];
__device__ __align__(16) __nv_bfloat16 g_yb[NR * CD];
__device__ float  g_x2[NR];
__device__ float  g_y2[NR];
__device__ double g_acc;

__device__ __forceinline__ uint32_t smem_u32(const void* p) {
    uint32_t a;
    asm("{ .reg .u64 t; cvta.to.shared.u64 t, %1; cvt.u32.u64 %0, t; }" : "=r"(a) : "l"(p));
    return a;
}
__device__ __forceinline__ void ldsm4(uint32_t* d, uint32_t addr) {
    asm volatile("ldmatrix.sync.aligned.m8n8.x4.shared.b16 {%0,%1,%2,%3}, [%4];"
                 : "=r"(d[0]), "=r"(d[1]), "=r"(d[2]), "=r"(d[3]) : "r"(addr));
}
__device__ __forceinline__ void mma_bf16(float* c, const uint32_t* a,
                                         uint32_t b0, uint32_t b1) {
    asm volatile(
        "mma.sync.aligned.m16n8k16.row.col.f32.bf16.bf16.f32 "
        "{%0,%1,%2,%3}, {%4,%5,%6,%7}, {%8,%9}, {%0,%1,%2,%3};"
        : "+f"(c[0]), "+f"(c[1]), "+f"(c[2]), "+f"(c[3])
        : "r"(a[0]), "r"(a[1]), "r"(a[2]), "r"(a[3]), "r"(b0), "r"(b1));
}

// ---------------- convert + transpose: (B,C,H,W) f32 -> [r][c] bf16 ----------------
__global__ void mmd_convert_kernel(const float* __restrict__ x,
                                   const float* __restrict__ y) {
    __shared__ float tile[32][33];
    int hwb = blockIdx.x * 32;
    int cb  = blockIdx.y * 32;
    int z   = blockIdx.z;            // batch(4) x arr(2)
    int b   = z & 3;
    const float* src = (z >> 2) ? y : x;
    __nv_bfloat16* dst = (z >> 2) ? g_yb : g_xb;
    int tx = threadIdx.x, ty = threadIdx.y;  // (32, 8)
    const float* s = src + (size_t)b * (CD * HWD) + hwb + tx;
#pragma unroll
    for (int i = 0; i < 4; ++i) {
        int c = cb + ty + i * 8;
        tile[ty + i * 8][tx] = s[(size_t)c * HWD];
    }
    __syncthreads();
#pragma unroll
    for (int i = 0; i < 4; ++i) {
        int hwl = ty + i * 8;
        int r = b * HWD + hwb + hwl;
        dst[(size_t)r * CD + cb + tx] = __float2bfloat16(tile[tx][hwl]);
    }
}

// ---------------- row norms (fp32 from original data) ----------------
__global__ void mmd_norm_kernel(const float* __restrict__ x,
                                const float* __restrict__ y) {
    int r = blockIdx.x * blockDim.x + threadIdx.x;
    if (r == 0 && blockIdx.y == 0) g_acc = 0.0;
    const float* p = blockIdx.y ? y : x;
    int b  = r >> 10;
    int hw = r & 1023;
    const float* base = p + (size_t)b * (CD * HWD) + hw;
    float s = 0.f;
#pragma unroll 8
    for (int c = 0; c < CD; ++c) {
        float v = base[(size_t)c * HWD];
        s = fmaf(v, v, s);
    }
    (blockIdx.y ? g_y2 : g_x2)[r] = s;
}

// ---------------- main: one 128x128 Gram tile per CTA ----------------
// mode 0: xx (sym, +1)   1: yy (sym, +1)   2: xy (full, -2)
__global__ void __launch_bounds__(256, 1)
mmd_mma_kernel(const float* __restrict__ sig, int mode) {
    extern __shared__ char smem[];
    const int AS = 0;
    const int BS = BM * ROWB;            // 67584
    const int RED = 2 * BM * ROWB;       // 135168

    int tid = threadIdx.x, lane = tid & 31, wid = tid >> 5;

    const __nv_bfloat16 *Ag, *Bg;
    const float *a2, *b2;
    double weight;
    int sym;
    if (mode == 0)      { Ag = g_xb; Bg = g_xb; a2 = g_x2; b2 = g_x2; weight =  1.0; sym = 1; }
    else if (mode == 1) { Ag = g_yb; Bg = g_yb; a2 = g_y2; b2 = g_y2; weight =  1.0; sym = 1; }
    else                { Ag = g_xb; Bg = g_yb; a2 = g_x2; b2 = g_y2; weight = -2.0; sym = 0; }

    int ti, tj;
    if (sym) {
        int b = blockIdx.x; ti = 0;
        while (b >= NTILE - ti) { b -= NTILE - ti; ++ti; }
        tj = ti + b;
    } else {
        ti = blockIdx.x / NTILE;
        tj = blockIdx.x % NTILE;
    }
    int rowA0 = ti * BM, rowB0 = tj * BM;
    int diag_tile = (sym && ti == tj);

    // stage tiles: 128 rows x 256 bf16 (32 uint4 chunks/row), 16 iters/tile
    const __nv_bfloat16* Arow = Ag + (size_t)rowA0 * CD;
    const __nv_bfloat16* Brow = Bg + (size_t)rowB0 * CD;
#pragma unroll
    for (int it = 0; it < 16; ++it) {
        int idx = tid + it * 256;
        int row = idx >> 5, ch = idx & 31;
        *(uint4*)(smem + AS + row * ROWB + ch * 16) =
            *((const uint4*)(Arow + (size_t)row * CD) + ch);
        *(uint4*)(smem + BS + row * ROWB + ch * 16) =
            *((const uint4*)(Brow + (size_t)row * CD) + ch);
    }
    __syncthreads();

    // warp layout: 4x2 grid of 32(M) x 64(N) per warp
    int wm = wid >> 1, wn = wid & 1;
    uint32_t sb = smem_u32(smem);
    // A ldmatrix.x4: lanes 0-15 -> rows 0-15 @k, lanes 16-31 -> rows 0-15 @k+8
    uint32_t abase = sb + AS + (uint32_t)(wm * 32 + (lane & 15)) * ROWB
                   + ((uint32_t)(lane >> 4) << 4);
    // B ldmatrix.x4: two n8 tiles; n = (lane&7) + ((lane>>4)<<3), k += ((lane>>3)&1)*8
    uint32_t bbase = sb + BS + (uint32_t)(wn * 64 + (lane & 7) + ((lane >> 4) << 3)) * ROWB
                   + (((uint32_t)(lane >> 3) & 1) << 4);

    float acc[2][8][4];
#pragma unroll
    for (int i = 0; i < 2; ++i)
#pragma unroll
        for (int j = 0; j < 8; ++j)
#pragma unroll
            for (int e = 0; e < 4; ++e) acc[i][j][e] = 0.f;

#pragma unroll
    for (int ks = 0; ks < 16; ++ks) {
        uint32_t koff = (uint32_t)ks << 5;   // 16 bf16 = 32 bytes
        uint32_t a0[4], a1[4];
        ldsm4(a0, abase + koff);
        ldsm4(a1, abase + 16 * ROWB + koff);
#pragma unroll
        for (int ntp = 0; ntp < 4; ++ntp) {
            uint32_t bfr[4];
            ldsm4(bfr, bbase + (uint32_t)(ntp * 16) * ROWB + koff);
            mma_bf16(acc[0][2 * ntp],     a0, bfr[0], bfr[1]);
            mma_bf16(acc[0][2 * ntp + 1], a0, bfr[2], bfr[3]);
            mma_bf16(acc[1][2 * ntp],     a1, bfr[0], bfr[1]);
            mma_bf16(acc[1][2 * ntp + 1], a1, bfr[2], bfr[3]);
        }
    }

    // epilogue: dist -> 5-exp sum, straight from accumulators
    float bet[5];
#pragma unroll
    for (int k = 0; k < 5; ++k) bet[k] = 0.5f / __ldg(&sig[k]);

    int g = lane >> 2, t = lane & 3;
    float part = 0.f;
#pragma unroll
    for (int mt = 0; mt < 2; ++mt) {
        int r0 = rowA0 + wm * 32 + mt * 16 + g;
        float a2lo = __ldg(a2 + r0);
        float a2hi = __ldg(a2 + r0 + 8);
#pragma unroll
        for (int nt = 0; nt < 8; ++nt) {
            int c0 = rowB0 + wn * 64 + nt * 8 + t * 2;
            float b2e[2] = { __ldg(b2 + c0), __ldg(b2 + c0 + 1) };
#pragma unroll
            for (int e = 0; e < 4; ++e) {
                int grow = (e < 2) ? r0 : r0 + 8;
                int gcol = c0 + (e & 1);
                if (diag_tile && grow == gcol) continue;  // diag added analytically
                float a2v = (e < 2) ? a2lo : a2hi;
                float d = fmaxf(a2v + b2e[e & 1] - 2.0f * acc[mt][nt][e], 0.f);
                float s = 0.f;
#pragma unroll
                for (int k = 0; k < 5; ++k) s += __expf(-bet[k] * d);
                part += s;
            }
        }
    }
    if (sym && ti != tj) part *= 2.0f;

    float* sred = (float*)(smem + RED);
    sred[tid] = part;
    __syncthreads();
    for (int s = 128; s > 0; s >>= 1) {
        if (tid < s) sred[tid] += sred[tid + s];
        __syncthreads();
    }
    if (tid == 0) atomicAdd(&g_acc, weight * (double)sred[0]);
}

__global__ void mmd_finalize(float* __restrict__ out) {
    // analytic diagonals of xx and yy: each row contributes Sum_k exp(0) = 5
    out[0] = (float)((g_acc + 2.0 * 5.0 * (double)NR) / ((double)NR * (double)NR));
}

#define SM_TOT (2 * BM * ROWB + 1024)

extern "C" void kernel_launch(void* const* d_in, const int* in_sizes, int n_in,
                              void* d_out, int out_size) {
    const float* x   = (const float*)d_in[0];
    const float* y   = (const float*)d_in[1];
    const float* sig = (const float*)d_in[2];
    float* out = (float*)d_out;

    cudaFuncSetAttribute(mmd_mma_kernel,
                         cudaFuncAttributeMaxDynamicSharedMemorySize, SM_TOT);

    mmd_convert_kernel<<<dim3(HWD / 32, CD / 32, 8), dim3(32, 8)>>>(x, y);
    mmd_norm_kernel<<<dim3(NR / 256, 2), 256>>>(x, y);

    int nsym  = NTILE * (NTILE + 1) / 2;  // 528
    int nfull = NTILE * NTILE;            // 1024
    mmd_mma_kernel<<<nsym,  256, SM_TOT>>>(sig, 0);
    mmd_mma_kernel<<<nsym,  256, SM_TOT>>>(sig, 1);
    mmd_mma_kernel<<<nfull, 256, SM_TOT>>>(sig, 2);

    mmd_finalize<<<1, 1>>>(out);
}

// round 7
// speedup vs baseline: 3.5690x; 1.1869x over previous
#include <cuda_runtime.h>
#include <cuda_bf16.h>
#include <cstdint>

// MK_MMDLoss R6: merged single-launch bf16 mma.sync Gram kernel.
//  - K chunked (2 x 128) -> smem 70.6KB -> 2 CTAs/SM (was 1 at 136KB).
//  - One 2080-block launch for xx/yy/xy (kills two launch-tail bubbles).
//  - exp() predicated off when beta*d >= 30 (underflow-irrelevant).
//  - Diagonal excluded per-element, added analytically in finalize.

#define NR    4096
#define CD    256
#define HWD   1024
#define BM    128
#define NTILE (NR / BM)     // 32
#define NSYM  (NTILE * (NTILE + 1) / 2)   // 528
#define NFULL (NTILE * NTILE)             // 1024
#define KC    128            // K chunk (bf16 elems)
#define ROWB  272            // smem row bytes: 256 + 16 pad (conflict-free ldmatrix)

#define AS    0
#define BS    (BM * ROWB)            // 34816
#define RED   (2 * BM * ROWB)        // 69632
#define SM_TOT (RED + 1024)          // 70656

__device__ __align__(16) __nv_bfloat16 g_xb[NR * CD];
__device__ __align__(16) __nv_bfloat16 g_yb[NR * CD];
__device__ float  g_x2[NR];
__device__ float  g_y2[NR];
__device__ double g_acc;

__device__ __forceinline__ uint32_t smem_u32(const void* p) {
    uint32_t a;
    asm("{ .reg .u64 t; cvta.to.shared.u64 t, %1; cvt.u32.u64 %0, t; }" : "=r"(a) : "l"(p));
    return a;
}
__device__ __forceinline__ void cp16(uint32_t dst, const void* src) {
    asm volatile("cp.async.cg.shared.global [%0], [%1], 16;" :: "r"(dst), "l"(src));
}
__device__ __forceinline__ void cp_commit_wait() {
    asm volatile("cp.async.commit_group;");
    asm volatile("cp.async.wait_group 0;" ::: "memory");
}
__device__ __forceinline__ void ldsm4(uint32_t* d, uint32_t addr) {
    asm volatile("ldmatrix.sync.aligned.m8n8.x4.shared.b16 {%0,%1,%2,%3}, [%4];"
                 : "=r"(d[0]), "=r"(d[1]), "=r"(d[2]), "=r"(d[3]) : "r"(addr));
}
__device__ __forceinline__ void mma_bf16(float* c, const uint32_t* a,
                                         uint32_t b0, uint32_t b1) {
    asm volatile(
        "mma.sync.aligned.m16n8k16.row.col.f32.bf16.bf16.f32 "
        "{%0,%1,%2,%3}, {%4,%5,%6,%7}, {%8,%9}, {%0,%1,%2,%3};"
        : "+f"(c[0]), "+f"(c[1]), "+f"(c[2]), "+f"(c[3])
        : "r"(a[0]), "r"(a[1]), "r"(a[2]), "r"(a[3]), "r"(b0), "r"(b1));
}

// ---------------- convert + transpose: (B,C,H,W) f32 -> [r][c] bf16 ----------------
__global__ void mmd_convert_kernel(const float* __restrict__ x,
                                   const float* __restrict__ y) {
    __shared__ float tile[32][33];
    int hwb = blockIdx.x * 32;
    int cb  = blockIdx.y * 32;
    int z   = blockIdx.z;            // batch(4) x arr(2)
    int b   = z & 3;
    const float* src = (z >> 2) ? y : x;
    __nv_bfloat16* dst = (z >> 2) ? g_yb : g_xb;
    int tx = threadIdx.x, ty = threadIdx.y;  // (32, 8)
    const float* s = src + (size_t)b * (CD * HWD) + hwb + tx;
#pragma unroll
    for (int i = 0; i < 4; ++i) {
        int c = cb + ty + i * 8;
        tile[ty + i * 8][tx] = s[(size_t)c * HWD];
    }
    __syncthreads();
#pragma unroll
    for (int i = 0; i < 4; ++i) {
        int hwl = ty + i * 8;
        int r = b * HWD + hwb + hwl;
        dst[(size_t)r * CD + cb + tx] = __float2bfloat16(tile[tx][hwl]);
    }
}

// ---------------- row norms (fp32 from original data) ----------------
__global__ void mmd_norm_kernel(const float* __restrict__ x,
                                const float* __restrict__ y) {
    int r = blockIdx.x * blockDim.x + threadIdx.x;
    if (r == 0 && blockIdx.y == 0) g_acc = 0.0;
    const float* p = blockIdx.y ? y : x;
    int b  = r >> 10;
    int hw = r & 1023;
    const float* base = p + (size_t)b * (CD * HWD) + hw;
    float s = 0.f;
#pragma unroll 8
    for (int c = 0; c < CD; ++c) {
        float v = base[(size_t)c * HWD];
        s = fmaf(v, v, s);
    }
    (blockIdx.y ? g_y2 : g_x2)[r] = s;
}

// ---------------- merged main: 2080 blocks = xx(528) + yy(528) + xy(1024) ----------------
__global__ void __launch_bounds__(256, 2)
mmd_mma_kernel(const float* __restrict__ sig) {
    extern __shared__ __align__(128) char smem[];
    int tid = threadIdx.x, lane = tid & 31, wid = tid >> 5;

    int bidx = blockIdx.x;
    int mode, idx;
    if (bidx < NSYM)            { mode = 0; idx = bidx; }
    else if (bidx < 2 * NSYM)   { mode = 1; idx = bidx - NSYM; }
    else                        { mode = 2; idx = bidx - 2 * NSYM; }

    const __nv_bfloat16 *Ag, *Bg;
    const float *a2, *b2;
    double weight;
    int sym;
    if (mode == 0)      { Ag = g_xb; Bg = g_xb; a2 = g_x2; b2 = g_x2; weight =  1.0; sym = 1; }
    else if (mode == 1) { Ag = g_yb; Bg = g_yb; a2 = g_y2; b2 = g_y2; weight =  1.0; sym = 1; }
    else                { Ag = g_xb; Bg = g_yb; a2 = g_x2; b2 = g_y2; weight = -2.0; sym = 0; }

    int ti, tj;
    if (sym) {
        int b = idx; ti = 0;
        while (b >= NTILE - ti) { b -= NTILE - ti; ++ti; }
        tj = ti + b;
    } else {
        ti = idx / NTILE;
        tj = idx % NTILE;
    }
    int rowA0 = ti * BM, rowB0 = tj * BM;
    int diag_tile = (sym && ti == tj);

    uint32_t sb = smem_u32(smem);

    // warp layout: 4x2 grid of 32(M) x 64(N) per warp
    int wm = wid >> 1, wn = wid & 1;
    uint32_t abase = sb + AS + (uint32_t)(wm * 32 + (lane & 15)) * ROWB
                   + ((uint32_t)(lane >> 4) << 4);
    uint32_t bbase = sb + BS + (uint32_t)(wn * 64 + (lane & 7) + ((lane >> 4) << 3)) * ROWB
                   + (((uint32_t)(lane >> 3) & 1) << 4);

    float acc[2][8][4];
#pragma unroll
    for (int i = 0; i < 2; ++i)
#pragma unroll
        for (int j = 0; j < 8; ++j)
#pragma unroll
            for (int e = 0; e < 4; ++e) acc[i][j][e] = 0.f;

    // per-thread load slots: idx = tid + it*256; row = idx>>4, ch = idx&15
    int lrow = tid >> 4, lch = tid & 15;

    for (int c = 0; c < CD / KC; ++c) {
        const __nv_bfloat16* Asrc = Ag + (size_t)rowA0 * CD + c * KC;
        const __nv_bfloat16* Bsrc = Bg + (size_t)rowB0 * CD + c * KC;
#pragma unroll
        for (int it = 0; it < 8; ++it) {
            int row = lrow + it * 16;
            cp16(sb + AS + row * ROWB + lch * 16, Asrc + (size_t)row * CD + lch * 8);
            cp16(sb + BS + row * ROWB + lch * 16, Bsrc + (size_t)row * CD + lch * 8);
        }
        cp_commit_wait();
        __syncthreads();

#pragma unroll
        for (int ks = 0; ks < KC / 16; ++ks) {
            uint32_t koff = (uint32_t)ks << 5;   // 16 bf16 = 32 bytes
            uint32_t a0[4], a1[4];
            ldsm4(a0, abase + koff);
            ldsm4(a1, abase + 16 * ROWB + koff);
#pragma unroll
            for (int ntp = 0; ntp < 4; ++ntp) {
                uint32_t bfr[4];
                ldsm4(bfr, bbase + (uint32_t)(ntp * 16) * ROWB + koff);
                mma_bf16(acc[0][2 * ntp],     a0, bfr[0], bfr[1]);
                mma_bf16(acc[0][2 * ntp + 1], a0, bfr[2], bfr[3]);
                mma_bf16(acc[1][2 * ntp],     a1, bfr[0], bfr[1]);
                mma_bf16(acc[1][2 * ntp + 1], a1, bfr[2], bfr[3]);
            }
        }
        if (c + 1 < CD / KC) __syncthreads();
    }

    // epilogue: dist -> 5-exp sum (exp predicated off when t >= 30: underflow)
    float bet[5];
#pragma unroll
    for (int k = 0; k < 5; ++k) bet[k] = 0.5f / __ldg(&sig[k]);

    int g = lane >> 2, t4 = lane & 3;
    float part = 0.f;
#pragma unroll
    for (int mt = 0; mt < 2; ++mt) {
        int r0 = rowA0 + wm * 32 + mt * 16 + g;
        float a2lo = __ldg(a2 + r0);
        float a2hi = __ldg(a2 + r0 + 8);
#pragma unroll
        for (int nt = 0; nt < 8; ++nt) {
            int c0 = rowB0 + wn * 64 + nt * 8 + t4 * 2;
            float b2e[2] = { __ldg(b2 + c0), __ldg(b2 + c0 + 1) };
#pragma unroll
            for (int e = 0; e < 4; ++e) {
                int grow = (e < 2) ? r0 : r0 + 8;
                int gcol = c0 + (e & 1);
                if (diag_tile && grow == gcol) continue;  // diag added analytically
                float a2v = (e < 2) ? a2lo : a2hi;
                float d = fmaxf(a2v + b2e[e & 1] - 2.0f * acc[mt][nt][e], 0.f);
                float s = 0.f;
#pragma unroll
                for (int k = 0; k < 5; ++k) {
                    float t = bet[k] * d;
                    if (t < 30.f) s += __expf(-t);
                }
                part += s;
            }
        }
    }
    if (sym && ti != tj) part *= 2.0f;

    float* sred = (float*)(smem + RED);
    sred[tid] = part;
    __syncthreads();
    for (int s = 128; s > 0; s >>= 1) {
        if (tid < s) sred[tid] += sred[tid + s];
        __syncthreads();
    }
    if (tid == 0) atomicAdd(&g_acc, weight * (double)sred[0]);
}

__global__ void mmd_finalize(float* __restrict__ out) {
    // analytic diagonals of xx and yy: each row contributes Sum_k exp(0) = 5
    out[0] = (float)((g_acc + 2.0 * 5.0 * (double)NR) / ((double)NR * (double)NR));
}

extern "C" void kernel_launch(void* const* d_in, const int* in_sizes, int n_in,
                              void* d_out, int out_size) {
    const float* x   = (const float*)d_in[0];
    const float* y   = (const float*)d_in[1];
    const float* sig = (const float*)d_in[2];
    float* out = (float*)d_out;

    cudaFuncSetAttribute(mmd_mma_kernel,
                         cudaFuncAttributeMaxDynamicSharedMemorySize, SM_TOT);

    mmd_convert_kernel<<<dim3(HWD / 32, CD / 32, 8), dim3(32, 8)>>>(x, y);
    mmd_norm_kernel<<<dim3(NR / 256, 2), 256>>>(x, y);

    mmd_mma_kernel<<<2 * NSYM + NFULL, 256, SM_TOT>>>(sig);

    mmd_finalize<<<1, 1>>>(out);
}

// round 8
// speedup vs baseline: 3.6084x; 1.0111x over previous
#include <cuda_runtime.h>
#include <cuda_bf16.h>
#include <cstdint>

// MK_MMDLoss R7: pipelined bf16 mma.sync Gram kernel.
//  - K split 4x64, double-buffered cp.async (depth 2) -> load latency hidden.
//  - finalize fused into main kernel (threadfence + ticket, replay-safe).
//  - shfl warp reduction instead of smem tree.
//  - Diagonal excluded per-element, added analytically.

#define NR    4096
#define CD    256
#define HWD   1024
#define BM    128
#define NTILE (NR / BM)     // 32
#define NSYM  (NTILE * (NTILE + 1) / 2)   // 528
#define NFULL (NTILE * NTILE)             // 1024
#define NBLK  (2 * NSYM + NFULL)          // 2080
#define KCH   64             // K chunk (bf16 elems)
#define NCHK  (CD / KCH)     // 4
#define ROWB  144            // smem row bytes: 128 + 16 pad (conflict-free ldmatrix)
#define ATILE (BM * ROWB)    // 18432
#define STG   (2 * ATILE)    // 36864 per stage (A+B)
#define SM_RED (2 * STG)     // 73728
#define SM_TOT (SM_RED + 64)

__device__ __align__(16) __nv_bfloat16 g_xb[NR * CD];
__device__ __align__(16) __nv_bfloat16 g_yb[NR * CD];
__device__ float  g_x2[NR];
__device__ float  g_y2[NR];
__device__ double g_acc;
__device__ unsigned int g_done = 0;

__device__ __forceinline__ uint32_t smem_u32(const void* p) {
    uint32_t a;
    asm("{ .reg .u64 t; cvta.to.shared.u64 t, %1; cvt.u32.u64 %0, t; }" : "=r"(a) : "l"(p));
    return a;
}
__device__ __forceinline__ void cp16(uint32_t dst, const void* src) {
    asm volatile("cp.async.cg.shared.global [%0], [%1], 16;" :: "r"(dst), "l"(src));
}
__device__ __forceinline__ void cp_commit() {
    asm volatile("cp.async.commit_group;");
}
__device__ __forceinline__ void cp_wait1() {
    asm volatile("cp.async.wait_group 1;" ::: "memory");
}
__device__ __forceinline__ void cp_wait0() {
    asm volatile("cp.async.wait_group 0;" ::: "memory");
}
__device__ __forceinline__ void ldsm4(uint32_t* d, uint32_t addr) {
    asm volatile("ldmatrix.sync.aligned.m8n8.x4.shared.b16 {%0,%1,%2,%3}, [%4];"
                 : "=r"(d[0]), "=r"(d[1]), "=r"(d[2]), "=r"(d[3]) : "r"(addr));
}
__device__ __forceinline__ void mma_bf16(float* c, const uint32_t* a,
                                         uint32_t b0, uint32_t b1) {
    asm volatile(
        "mma.sync.aligned.m16n8k16.row.col.f32.bf16.bf16.f32 "
        "{%0,%1,%2,%3}, {%4,%5,%6,%7}, {%8,%9}, {%0,%1,%2,%3};"
        : "+f"(c[0]), "+f"(c[1]), "+f"(c[2]), "+f"(c[3])
        : "r"(a[0]), "r"(a[1]), "r"(a[2]), "r"(a[3]), "r"(b0), "r"(b1));
}

// ---------------- convert + transpose: (B,C,H,W) f32 -> [r][c] bf16 ----------------
__global__ void mmd_convert_kernel(const float* __restrict__ x,
                                   const float* __restrict__ y) {
    __shared__ float tile[32][33];
    int hwb = blockIdx.x * 32;
    int cb  = blockIdx.y * 32;
    int z   = blockIdx.z;            // batch(4) x arr(2)
    int b   = z & 3;
    const float* src = (z >> 2) ? y : x;
    __nv_bfloat16* dst = (z >> 2) ? g_yb : g_xb;
    int tx = threadIdx.x, ty = threadIdx.y;  // (32, 8)
    const float* s = src + (size_t)b * (CD * HWD) + hwb + tx;
#pragma unroll
    for (int i = 0; i < 4; ++i) {
        int c = cb + ty + i * 8;
        tile[ty + i * 8][tx] = s[(size_t)c * HWD];
    }
    __syncthreads();
#pragma unroll
    for (int i = 0; i < 4; ++i) {
        int hwl = ty + i * 8;
        int r = b * HWD + hwb + hwl;
        dst[(size_t)r * CD + cb + tx] = __float2bfloat16(tile[tx][hwl]);
    }
}

// ---------------- row norms (fp32 from original data) ----------------
__global__ void mmd_norm_kernel(const float* __restrict__ x,
                                const float* __restrict__ y) {
    int r = blockIdx.x * blockDim.x + threadIdx.x;
    if (r == 0 && blockIdx.y == 0) g_acc = 0.0;
    const float* p = blockIdx.y ? y : x;
    int b  = r >> 10;
    int hw = r & 1023;
    const float* base = p + (size_t)b * (CD * HWD) + hw;
    float s = 0.f;
#pragma unroll 8
    for (int c = 0; c < CD; ++c) {
        float v = base[(size_t)c * HWD];
        s = fmaf(v, v, s);
    }
    (blockIdx.y ? g_y2 : g_x2)[r] = s;
}

// ---------------- merged main: 2080 blocks = xx(528) + yy(528) + xy(1024) ----------------
__global__ void __launch_bounds__(256, 2)
mmd_mma_kernel(const float* __restrict__ sig, float* __restrict__ out) {
    extern __shared__ __align__(128) char smem[];
    int tid = threadIdx.x, lane = tid & 31, wid = tid >> 5;

    int bidx = blockIdx.x;
    int mode, idx;
    if (bidx < NSYM)            { mode = 0; idx = bidx; }
    else if (bidx < 2 * NSYM)   { mode = 1; idx = bidx - NSYM; }
    else                        { mode = 2; idx = bidx - 2 * NSYM; }

    const __nv_bfloat16 *Ag, *Bg;
    const float *a2, *b2;
    double weight;
    int sym;
    if (mode == 0)      { Ag = g_xb; Bg = g_xb; a2 = g_x2; b2 = g_x2; weight =  1.0; sym = 1; }
    else if (mode == 1) { Ag = g_yb; Bg = g_yb; a2 = g_y2; b2 = g_y2; weight =  1.0; sym = 1; }
    else                { Ag = g_xb; Bg = g_yb; a2 = g_x2; b2 = g_y2; weight = -2.0; sym = 0; }

    int ti, tj;
    if (sym) {
        int b = idx; ti = 0;
        while (b >= NTILE - ti) { b -= NTILE - ti; ++ti; }
        tj = ti + b;
    } else {
        ti = idx / NTILE;
        tj = idx % NTILE;
    }
    int rowA0 = ti * BM, rowB0 = tj * BM;
    int diag_tile = (sym && ti == tj);

    uint32_t sb = smem_u32(smem);
    const __nv_bfloat16* Abase = Ag + (size_t)rowA0 * CD;
    const __nv_bfloat16* Bbase = Bg + (size_t)rowB0 * CD;

    // loader slots: 1024 cp16 per matrix per chunk; idx = tid + it*256
    int lrow = tid >> 3, lch = tid & 7;   // base row 0..31, chunk-of-16B 0..7

    // issue chunks 0 and 1
#pragma unroll
    for (int s = 0; s < 2; ++s) {
        uint32_t as = sb + s * STG, bs = as + ATILE;
#pragma unroll
        for (int it = 0; it < 4; ++it) {
            int row = lrow + it * 32;
            cp16(as + row * ROWB + lch * 16, Abase + (size_t)row * CD + s * KCH + lch * 8);
            cp16(bs + row * ROWB + lch * 16, Bbase + (size_t)row * CD + s * KCH + lch * 8);
        }
        cp_commit();
    }

    // warp layout: 4x2 grid of 32(M) x 64(N) per warp
    int wm = wid >> 1, wn = wid & 1;
    uint32_t arow = (uint32_t)(wm * 32 + (lane & 15)) * ROWB + ((uint32_t)(lane >> 4) << 4);
    uint32_t brow = (uint32_t)(wn * 64 + (lane & 7) + ((lane >> 4) << 3)) * ROWB
                  + (((uint32_t)(lane >> 3) & 1) << 4);

    float acc[2][8][4];
#pragma unroll
    for (int i = 0; i < 2; ++i)
#pragma unroll
        for (int j = 0; j < 8; ++j)
#pragma unroll
            for (int e = 0; e < 4; ++e) acc[i][j][e] = 0.f;

#pragma unroll
    for (int c = 0; c < NCHK; ++c) {
        if (c == NCHK - 1) cp_wait0(); else cp_wait1();
        __syncthreads();

        uint32_t abase = sb + (c & 1) * STG + arow;
        uint32_t bbase = sb + (c & 1) * STG + ATILE + brow;
#pragma unroll
        for (int ks = 0; ks < KCH / 16; ++ks) {
            uint32_t koff = (uint32_t)ks << 5;   // 16 bf16 = 32 bytes
            uint32_t a0[4], a1[4];
            ldsm4(a0, abase + koff);
            ldsm4(a1, abase + 16 * ROWB + koff);
#pragma unroll
            for (int ntp = 0; ntp < 4; ++ntp) {
                uint32_t bfr[4];
                ldsm4(bfr, bbase + (uint32_t)(ntp * 16) * ROWB + koff);
                mma_bf16(acc[0][2 * ntp],     a0, bfr[0], bfr[1]);
                mma_bf16(acc[0][2 * ntp + 1], a0, bfr[2], bfr[3]);
                mma_bf16(acc[1][2 * ntp],     a1, bfr[0], bfr[1]);
                mma_bf16(acc[1][2 * ntp + 1], a1, bfr[2], bfr[3]);
            }
        }
        __syncthreads();   // all reads of buf (c&1) done before refill

        if (c + 2 < NCHK) {
            int s = c & 1, ch = c + 2;
            uint32_t as = sb + s * STG, bs = as + ATILE;
#pragma unroll
            for (int it = 0; it < 4; ++it) {
                int row = lrow + it * 32;
                cp16(as + row * ROWB + lch * 16, Abase + (size_t)row * CD + ch * KCH + lch * 8);
                cp16(bs + row * ROWB + lch * 16, Bbase + (size_t)row * CD + ch * KCH + lch * 8);
            }
            cp_commit();
        }
    }

    // epilogue: dist -> 5-exp sum (exp predicated off when t >= 30: underflow)
    float bet[5];
#pragma unroll
    for (int k = 0; k < 5; ++k) bet[k] = 0.5f / __ldg(&sig[k]);

    int g = lane >> 2, t4 = lane & 3;
    float part = 0.f;
#pragma unroll
    for (int mt = 0; mt < 2; ++mt) {
        int r0 = rowA0 + wm * 32 + mt * 16 + g;
        float a2lo = __ldg(a2 + r0);
        float a2hi = __ldg(a2 + r0 + 8);
#pragma unroll
        for (int nt = 0; nt < 8; ++nt) {
            int c0 = rowB0 + wn * 64 + nt * 8 + t4 * 2;
            float b2e[2] = { __ldg(b2 + c0), __ldg(b2 + c0 + 1) };
#pragma unroll
            for (int e = 0; e < 4; ++e) {
                int grow = (e < 2) ? r0 : r0 + 8;
                int gcol = c0 + (e & 1);
                if (diag_tile && grow == gcol) continue;  // diag added analytically
                float a2v = (e < 2) ? a2lo : a2hi;
                float d = fmaxf(a2v + b2e[e & 1] - 2.0f * acc[mt][nt][e], 0.f);
                float s = 0.f;
#pragma unroll
                for (int k = 0; k < 5; ++k) {
                    float t = bet[k] * d;
                    if (t < 30.f) s += __expf(-t);
                }
                part += s;
            }
        }
    }
    if (sym && ti != tj) part *= 2.0f;

    // warp reduce + cross-warp
#pragma unroll
    for (int o = 16; o > 0; o >>= 1)
        part += __shfl_down_sync(0xFFFFFFFFu, part, o);
    float* sred = (float*)(smem + SM_RED);
    if (lane == 0) sred[wid] = part;
    __syncthreads();
    if (tid == 0) {
        float tot = 0.f;
#pragma unroll
        for (int w = 0; w < 8; ++w) tot += sred[w];
        atomicAdd(&g_acc, weight * (double)tot);
        __threadfence();
        unsigned int ticket = atomicAdd(&g_done, 1u);
        if (ticket == NBLK - 1) {
            g_done = 0;   // replay-safe reset
            // analytic diagonals of xx and yy: each row contributes 5
            out[0] = (float)((g_acc + 2.0 * 5.0 * (double)NR)
                             / ((double)NR * (double)NR));
        }
    }
}

extern "C" void kernel_launch(void* const* d_in, const int* in_sizes, int n_in,
                              void* d_out, int out_size) {
    const float* x   = (const float*)d_in[0];
    const float* y   = (const float*)d_in[1];
    const float* sig = (const float*)d_in[2];
    float* out = (float*)d_out;

    cudaFuncSetAttribute(mmd_mma_kernel,
                         cudaFuncAttributeMaxDynamicSharedMemorySize, SM_TOT);

    mmd_convert_kernel<<<dim3(HWD / 32, CD / 32, 8), dim3(32, 8)>>>(x, y);
    mmd_norm_kernel<<<dim3(NR / 256, 2), 256>>>(x, y);

    mmd_mma_kernel<<<NBLK, 256, SM_TOT>>>(sig, out);
}